// round 2
// baseline (speedup 1.0000x reference)
#include <cuda_runtime.h>
#include <cuda_bf16.h>
#include <math.h>

#define N_NODES  50000
#define N_EDGES  600000
#define N_GRAPHS 64
#define IN_C  128
#define HID_C 128
#define OUT_C 64

// ---------------- scratch (device globals; no allocation allowed) ----------------
__device__ int   d_cnt[N_NODES];        // in-degree histogram (w/o self loop)
__device__ int   d_rowptr[N_NODES + 1]; // CSR row pointers (by dst)
__device__ int   d_cursor[N_NODES];     // scatter cursors
__device__ int   d_col[N_EDGES];        // CSR column (src) indices
__device__ float d_dinv[N_NODES];       // rsqrt(deg+1)
__device__ float d_g [N_NODES * HID_C]; // dinv * (x @ W1)
__device__ float d_g2[N_NODES * HID_C]; // dinv * relu(layer1 out)
__device__ float d_pool[N_GRAPHS * HID_C];
__device__ int   d_start[N_GRAPHS + 1]; // graph segment starts in sorted batch

// ---------------- init (must re-run every graph replay) ----------------
__global__ void k_init() {
    int i = blockIdx.x * blockDim.x + threadIdx.x;
    if (i < N_NODES) d_cnt[i] = 0;
    if (i < N_GRAPHS * HID_C) d_pool[i] = 0.0f;
    if (i <= N_GRAPHS) d_start[i] = N_NODES;
}

// ---------------- degree histogram over dst (int32 edge indices!) ----------------
__global__ void k_hist(const int* __restrict__ edge) {
    int e = blockIdx.x * blockDim.x + threadIdx.x;
    if (e >= N_EDGES) return;
    unsigned dst = (unsigned)edge[N_EDGES + e];
    if (dst < N_NODES) atomicAdd(&d_cnt[dst], 1);
}

// ---------------- single-block scan: rowptr, cursor, dinv ----------------
__global__ void k_scan() {
    __shared__ int wsum[32];
    int tid = threadIdx.x;
    int lane = tid & 31, wid = tid >> 5;
    int offset = 0;
    for (int base = 0; base < N_NODES; base += 1024) {
        int i = base + tid;
        int v = (i < N_NODES) ? d_cnt[i] : 0;
        int x = v;
        #pragma unroll
        for (int d = 1; d < 32; d <<= 1) {
            int t = __shfl_up_sync(0xffffffffu, x, d);
            if (lane >= d) x += t;
        }
        if (lane == 31) wsum[wid] = x;
        __syncthreads();
        if (wid == 0) {
            int y = wsum[lane];
            #pragma unroll
            for (int d = 1; d < 32; d <<= 1) {
                int t = __shfl_up_sync(0xffffffffu, y, d);
                if (lane >= d) y += t;
            }
            wsum[lane] = y;
        }
        __syncthreads();
        int excl = offset + (x - v) + (wid > 0 ? wsum[wid - 1] : 0);
        if (i < N_NODES) {
            d_rowptr[i] = excl;
            d_cursor[i] = excl;
            d_dinv[i] = rsqrtf((float)(v + 1));
        }
        offset += wsum[31];
        __syncthreads();
    }
    if (tid == 0) d_rowptr[N_NODES] = offset;
}

// ---------------- CSR scatter ----------------
__global__ void k_scatter(const int* __restrict__ edge) {
    int e = blockIdx.x * blockDim.x + threadIdx.x;
    if (e >= N_EDGES) return;
    unsigned src = (unsigned)edge[e];
    unsigned dst = (unsigned)edge[N_EDGES + e];
    if (src >= N_NODES || dst >= N_NODES) return;
    int p = atomicAdd(&d_cursor[dst], 1);
    d_col[p] = (int)src;
}

// ---------------- graph segment boundaries (batch is sorted int32) ----------------
__global__ void k_bound(const int* __restrict__ batch) {
    int i = blockIdx.x * blockDim.x + threadIdx.x;
    if (i >= N_NODES) return;
    int b  = min(max(batch[i], 0), N_GRAPHS - 1);
    int bp = (i == 0) ? -1 : min(max(batch[i - 1], 0), N_GRAPHS - 1);
    for (int gg = bp + 1; gg <= b; gg++) d_start[gg] = i;
}

// ---------------- GEMM1: g = dinv * (x @ W1) ----------------
// 64x128 tile per block, W1 fully in smem, x tile transposed in smem.
#define GEMM_SMEM_BYTES ((16384 + 128 * 68) * 4)
__global__ __launch_bounds__(256) void k_gemm1(const float* __restrict__ x,
                                               const float* __restrict__ W1) {
    extern __shared__ float sm[];
    float* Ws = sm;                 // [128][128]
    float* Xs = sm + 16384;         // [128][68] (k-major, 68-stride pad, 16B aligned)
    const int XSS = 68;
    int row0 = blockIdx.x * 64;

    {
        const float4* W4 = (const float4*)W1;
        float4* Ws4 = (float4*)Ws;
        for (int i = threadIdx.x; i < 4096; i += 256) Ws4[i] = W4[i];
    }
    for (int i = threadIdx.x; i < 64 * 32; i += 256) {
        int r = i >> 5, c4 = i & 31;
        int gr = row0 + r;
        float4 v = make_float4(0.f, 0.f, 0.f, 0.f);
        if (gr < N_NODES) v = ((const float4*)(x + (size_t)gr * IN_C))[c4];
        int c = c4 * 4;
        Xs[(c + 0) * XSS + r] = v.x;
        Xs[(c + 1) * XSS + r] = v.y;
        Xs[(c + 2) * XSS + r] = v.z;
        Xs[(c + 3) * XSS + r] = v.w;
    }
    __syncthreads();

    int tc = (threadIdx.x & 15) * 8;   // output col start
    int tr = (threadIdx.x >> 4) * 4;   // output row start (in tile)
    float acc[4][8];
    #pragma unroll
    for (int i = 0; i < 4; i++)
        #pragma unroll
        for (int j = 0; j < 8; j++) acc[i][j] = 0.f;

    #pragma unroll 4
    for (int k = 0; k < 128; k++) {
        float4 xv = *(const float4*)&Xs[k * XSS + tr];
        float4 w0 = *(const float4*)&Ws[k * 128 + tc];
        float4 w1 = *(const float4*)&Ws[k * 128 + tc + 4];
        float xa[4] = {xv.x, xv.y, xv.z, xv.w};
        float wa[8] = {w0.x, w0.y, w0.z, w0.w, w1.x, w1.y, w1.z, w1.w};
        #pragma unroll
        for (int i = 0; i < 4; i++)
            #pragma unroll
            for (int j = 0; j < 8; j++)
                acc[i][j] = fmaf(xa[i], wa[j], acc[i][j]);
    }

    #pragma unroll
    for (int i = 0; i < 4; i++) {
        int r = row0 + tr + i;
        if (r < N_NODES) {
            float dv = d_dinv[r];
            float4 o0 = make_float4(acc[i][0] * dv, acc[i][1] * dv,
                                    acc[i][2] * dv, acc[i][3] * dv);
            float4 o1 = make_float4(acc[i][4] * dv, acc[i][5] * dv,
                                    acc[i][6] * dv, acc[i][7] * dv);
            *(float4*)(d_g + (size_t)r * HID_C + tc)     = o0;
            *(float4*)(d_g + (size_t)r * HID_C + tc + 4) = o1;
        }
    }
}

// ---------------- layer-1 aggregate + bias + relu + rescale ----------------
// One warp per node, float4 per lane (128 dims / 32 lanes).
__global__ __launch_bounds__(256) void k_agg1(const float* __restrict__ b1) {
    int gw   = (blockIdx.x * blockDim.x + threadIdx.x) >> 5;
    int lane = threadIdx.x & 31;
    if (gw >= N_NODES) return;
    int j = gw;
    const float4* g4 = (const float4*)d_g;
    float4 s = g4[(size_t)j * 32 + lane];       // self loop
    int e0 = d_rowptr[j], e1 = d_rowptr[j + 1];
    for (int e = e0; e < e1; e++) {
        int sn = d_col[e];
        float4 v = __ldg(&g4[(size_t)sn * 32 + lane]);
        s.x += v.x; s.y += v.y; s.z += v.z; s.w += v.w;
    }
    float dj = d_dinv[j];
    float4 bb = ((const float4*)b1)[lane];
    float4 o;
    o.x = fmaxf(fmaf(s.x, dj, bb.x), 0.f) * dj;
    o.y = fmaxf(fmaf(s.y, dj, bb.y), 0.f) * dj;
    o.z = fmaxf(fmaf(s.z, dj, bb.z), 0.f) * dj;
    o.w = fmaxf(fmaf(s.w, dj, bb.w), 0.f) * dj;
    ((float4*)d_g2)[(size_t)j * 32 + lane] = o;
}

// ---------------- layer-2 aggregate fused with mean-pool accumulation ----------------
// Warp per 64-node contiguous strip; batch is sorted, so flush on graph change.
__global__ __launch_bounds__(256) void k_agg2(const int* __restrict__ batch) {
    int gw   = (blockIdx.x * blockDim.x + threadIdx.x) >> 5;
    int lane = threadIdx.x & 31;
    int j0 = gw * 64;
    if (j0 >= N_NODES) return;
    int j1 = min(j0 + 64, N_NODES);
    const float4* g4 = (const float4*)d_g2;
    float4 acc = make_float4(0.f, 0.f, 0.f, 0.f);
    int curg = min(max(batch[j0], 0), N_GRAPHS - 1);
    for (int j = j0; j < j1; j++) {
        int bg = min(max(batch[j], 0), N_GRAPHS - 1);
        if (bg != curg) {
            float* p = &d_pool[curg * HID_C + lane * 4];
            atomicAdd(p + 0, acc.x); atomicAdd(p + 1, acc.y);
            atomicAdd(p + 2, acc.z); atomicAdd(p + 3, acc.w);
            acc = make_float4(0.f, 0.f, 0.f, 0.f);
            curg = bg;
        }
        float4 s = g4[(size_t)j * 32 + lane];   // self loop
        int e0 = d_rowptr[j], e1 = d_rowptr[j + 1];
        for (int e = e0; e < e1; e++) {
            int sn = d_col[e];
            float4 v = __ldg(&g4[(size_t)sn * 32 + lane]);
            s.x += v.x; s.y += v.y; s.z += v.z; s.w += v.w;
        }
        float dj = d_dinv[j];
        acc.x = fmaf(s.x, dj, acc.x);
        acc.y = fmaf(s.y, dj, acc.y);
        acc.z = fmaf(s.z, dj, acc.z);
        acc.w = fmaf(s.w, dj, acc.w);
    }
    float* p = &d_pool[curg * HID_C + lane * 4];
    atomicAdd(p + 0, acc.x); atomicAdd(p + 1, acc.y);
    atomicAdd(p + 2, acc.z); atomicAdd(p + 3, acc.w);
}

// ---------------- final: out = (pool/cnt) @ W2 + b2 ----------------
__global__ void k_final(const float* __restrict__ W2, const float* __restrict__ b2,
                        float* __restrict__ out) {
    __shared__ float ps[HID_C];
    int g = blockIdx.x;
    int t = threadIdx.x; // 128 threads
    int cnt = d_start[g + 1] - d_start[g];
    float inv = 1.0f / (float)max(cnt, 1);
    ps[t] = d_pool[g * HID_C + t];
    __syncthreads();
    if (t < OUT_C) {
        float sum = 0.f;
        #pragma unroll
        for (int k = 0; k < HID_C; k++)
            sum = fmaf(ps[k], W2[k * OUT_C + t], sum);
        out[g * OUT_C + t] = sum * inv + (cnt > 0 ? b2[t] : 0.f);
    }
}

// ---------------- launch ----------------
extern "C" void kernel_launch(void* const* d_in, const int* in_sizes, int n_in,
                              void* d_out, int out_size) {
    const float *x = nullptr, *W1 = nullptr, *b1 = nullptr, *W2 = nullptr, *b2 = nullptr;
    const int *edge = nullptr, *batch = nullptr;
    for (int i = 0; i < n_in; i++) {
        switch (in_sizes[i]) {
            case N_NODES * IN_C:  x     = (const float*)d_in[i]; break; // 6,400,000
            case IN_C * HID_C:    W1    = (const float*)d_in[i]; break; // 16,384
            case HID_C:           b1    = (const float*)d_in[i]; break; // 128
            case HID_C * OUT_C:   W2    = (const float*)d_in[i]; break; // 8,192
            case OUT_C:           b2    = (const float*)d_in[i]; break; // 64
            case 2 * N_EDGES:     edge  = (const int*)d_in[i];   break; // 1,200,000
            case N_NODES:         batch = (const int*)d_in[i];   break; // 50,000
            default: break;
        }
    }

    cudaFuncSetAttribute(k_gemm1, cudaFuncAttributeMaxDynamicSharedMemorySize,
                         GEMM_SMEM_BYTES);

    k_init<<<(N_NODES + 255) / 256, 256>>>();
    k_hist<<<(N_EDGES + 255) / 256, 256>>>(edge);
    k_scan<<<1, 1024>>>();
    k_scatter<<<(N_EDGES + 255) / 256, 256>>>(edge);
    k_bound<<<(N_NODES + 255) / 256, 256>>>(batch);
    k_gemm1<<<(N_NODES + 63) / 64, 256, GEMM_SMEM_BYTES>>>(x, W1);
    k_agg1<<<(N_NODES + 7) / 8, 256>>>(b1);
    k_agg2<<<((N_NODES + 63) / 64 + 7) / 8, 256>>>(batch);
    k_final<<<N_GRAPHS, 128>>>(W2, b2, (float*)d_out);
}

// round 3
// speedup vs baseline: 1.1529x; 1.1529x over previous
#include <cuda_runtime.h>
#include <cuda_fp16.h>
#include <math.h>

#define N_NODES  50000
#define N_EDGES  600000
#define N_GRAPHS 64
#define IN_C  128
#define HID_C 128
#define OUT_C 64
#define NBLK  196            // ceil(50000/256)

// ---------------- scratch (device globals; no allocation allowed) ----------------
__device__ int    d_cnt[N_NODES];
__device__ int    d_rowptr[N_NODES + 1];
__device__ int    d_cursor[N_NODES];     // local-excl during scan, then cursors
__device__ int    d_part[NBLK];
__device__ int    d_col[N_EDGES];
__device__ float  d_dinv[N_NODES];
__device__ __half d_gh [N_NODES * HID_C];   // dinv * (x @ W1), fp16
__device__ __half d_g2h[N_NODES * HID_C];   // dinv * relu(...), fp16
__device__ float  d_pool[N_GRAPHS * HID_C];
__device__ int    d_start[N_GRAPHS + 1];

// ---------------- helpers ----------------
__device__ __forceinline__ float4 h4_to_f4(uint2 u) {
    __half2 a = *(__half2*)&u.x, b = *(__half2*)&u.y;
    float2 fa = __half22float2(a), fb = __half22float2(b);
    return make_float4(fa.x, fa.y, fb.x, fb.y);
}
__device__ __forceinline__ uint2 f4_to_h4(float4 v) {
    __half2 a = __floats2half2_rn(v.x, v.y), b = __floats2half2_rn(v.z, v.w);
    uint2 u; u.x = *(unsigned*)&a; u.y = *(unsigned*)&b; return u;
}

// ---------------- init: zero cnt + pool ----------------
__global__ void k_init() {
    int i = blockIdx.x * blockDim.x + threadIdx.x;
    if (i < N_NODES) d_cnt[i] = 0;
    if (i < N_GRAPHS * HID_C) d_pool[i] = 0.0f;
}

// ---------------- histogram over dst ----------------
__global__ void k_hist(const int* __restrict__ edge) {
    int e = blockIdx.x * blockDim.x + threadIdx.x;
    if (e >= N_EDGES) return;
    unsigned dst = (unsigned)edge[N_EDGES + e];
    if (dst < N_NODES) atomicAdd(&d_cnt[dst], 1);
}

// ---------------- scan phase A: per-block exclusive scan + block totals ----------------
__global__ __launch_bounds__(256) void k_scanA() {
    __shared__ int wsum[8];
    int tid = threadIdx.x, lane = tid & 31, wid = tid >> 5;
    int i = blockIdx.x * 256 + tid;
    int v = (i < N_NODES) ? d_cnt[i] : 0;
    int x = v;
    #pragma unroll
    for (int d = 1; d < 32; d <<= 1) {
        int t = __shfl_up_sync(0xffffffffu, x, d);
        if (lane >= d) x += t;
    }
    if (lane == 31) wsum[wid] = x;
    __syncthreads();
    if (wid == 0 && lane < 8) {
        int y = wsum[lane];
        #pragma unroll
        for (int d = 1; d < 8; d <<= 1) {
            int t = __shfl_up_sync(0x000000ffu, y, d);
            if (lane >= d) y += t;
        }
        wsum[lane] = y;
    }
    __syncthreads();
    int excl = (x - v) + (wid > 0 ? wsum[wid - 1] : 0);
    if (i < N_NODES) d_cursor[i] = excl;   // local exclusive
    if (tid == 0) d_part[blockIdx.x] = wsum[7];
}

// ---------------- scan phase B: scan the 196 block totals ----------------
__global__ __launch_bounds__(256) void k_scanB() {
    __shared__ int s[256];
    int t = threadIdx.x;
    int v = (t < NBLK) ? d_part[t] : 0;
    s[t] = v; __syncthreads();
    for (int off = 1; off < 256; off <<= 1) {
        int u = (t >= off) ? s[t - off] : 0;
        __syncthreads();
        s[t] += u;
        __syncthreads();
    }
    if (t < NBLK) d_part[t] = s[t] - v;          // exclusive
    if (t == 255) d_rowptr[N_NODES] = s[255];    // total
}

// ---------------- scan phase C: fixup + dinv ----------------
__global__ __launch_bounds__(256) void k_scanC() {
    int i = blockIdx.x * 256 + threadIdx.x;
    if (i >= N_NODES) return;
    int v = d_cursor[i] + d_part[blockIdx.x];
    d_rowptr[i] = v;
    d_cursor[i] = v;
    d_dinv[i] = rsqrtf((float)(d_cnt[i] + 1));
}

// ---------------- CSR scatter ----------------
__global__ void k_scatter(const int* __restrict__ edge) {
    int e = blockIdx.x * blockDim.x + threadIdx.x;
    if (e >= N_EDGES) return;
    unsigned src = (unsigned)edge[e];
    unsigned dst = (unsigned)edge[N_EDGES + e];
    if (src >= N_NODES || dst >= N_NODES) return;
    int p = atomicAdd(&d_cursor[dst], 1);
    d_col[p] = (int)src;
}

// ---------------- graph segment boundaries (batch sorted int32) ----------------
__global__ void k_bound(const int* __restrict__ batch) {
    int i = blockIdx.x * blockDim.x + threadIdx.x;
    if (i >= N_NODES) return;
    int b  = min(max(batch[i], 0), N_GRAPHS - 1);
    int bp = (i == 0) ? -1 : min(max(batch[i - 1], 0), N_GRAPHS - 1);
    for (int gg = bp + 1; gg <= b; gg++) d_start[gg] = i;
    if (i == N_NODES - 1)
        for (int gg = b + 1; gg <= N_GRAPHS; gg++) d_start[gg] = N_NODES;
}

// ---------------- GEMM1: d_gh = fp16( dinv * (x @ W1) ) ----------------
// 128x128 tile per block, 8x8 micro-tile, 256 threads.
#define GEMM_SMEM_BYTES ((128 * 128 + 128 * 129) * 4)
__global__ __launch_bounds__(256) void k_gemm1(const float* __restrict__ x,
                                               const float* __restrict__ W1) {
    extern __shared__ float sm[];
    float* Ws = sm;                  // [128][128] k-major
    float* Xs = sm + 128 * 128;      // [128 rows][129] row-major, padded
    int row0 = blockIdx.x * 128;

    {
        const float4* W4 = (const float4*)W1;
        float4* Ws4 = (float4*)Ws;
        for (int i = threadIdx.x; i < 4096; i += 256) Ws4[i] = W4[i];
    }
    for (int i = threadIdx.x; i < 4096; i += 256) {
        int r = i >> 5, c4 = i & 31;
        int gr = row0 + r;
        float4 v = make_float4(0.f, 0.f, 0.f, 0.f);
        if (gr < N_NODES) v = ((const float4*)(x + (size_t)gr * IN_C))[c4];
        float* dp = &Xs[r * 129 + c4 * 4];
        dp[0] = v.x; dp[1] = v.y; dp[2] = v.z; dp[3] = v.w;
    }
    __syncthreads();

    int tc = (threadIdx.x & 15) * 8;
    int tr = (threadIdx.x >> 4) * 8;
    float acc[8][8];
    #pragma unroll
    for (int i = 0; i < 8; i++)
        #pragma unroll
        for (int j = 0; j < 8; j++) acc[i][j] = 0.f;

    #pragma unroll 2
    for (int k = 0; k < 128; k++) {
        float xa[8];
        #pragma unroll
        for (int i = 0; i < 8; i++) xa[i] = Xs[(tr + i) * 129 + k];
        float4 w0 = *(const float4*)&Ws[k * 128 + tc];
        float4 w1 = *(const float4*)&Ws[k * 128 + tc + 4];
        float wa[8] = {w0.x, w0.y, w0.z, w0.w, w1.x, w1.y, w1.z, w1.w};
        #pragma unroll
        for (int i = 0; i < 8; i++)
            #pragma unroll
            for (int j = 0; j < 8; j++)
                acc[i][j] = fmaf(xa[i], wa[j], acc[i][j]);
    }

    #pragma unroll
    for (int i = 0; i < 8; i++) {
        int r = row0 + tr + i;
        if (r < N_NODES) {
            float dv = d_dinv[r];
            uint2 lo = f4_to_h4(make_float4(acc[i][0] * dv, acc[i][1] * dv,
                                            acc[i][2] * dv, acc[i][3] * dv));
            uint2 hi = f4_to_h4(make_float4(acc[i][4] * dv, acc[i][5] * dv,
                                            acc[i][6] * dv, acc[i][7] * dv));
            uint4 u; u.x = lo.x; u.y = lo.y; u.z = hi.x; u.w = hi.y;
            *(uint4*)(&d_gh[(size_t)r * HID_C + tc]) = u;
        }
    }
}

// ---------------- layer-1 aggregate: warp per node, fp16 in/out ----------------
__global__ __launch_bounds__(256) void k_agg1(const float* __restrict__ b1) {
    int gw   = (blockIdx.x * blockDim.x + threadIdx.x) >> 5;
    int lane = threadIdx.x & 31;
    if (gw >= N_NODES) return;
    const uint2* g2 = (const uint2*)d_gh;   // 4 halfs per entry, node stride 32
    float4 s = h4_to_f4(g2[(size_t)gw * 32 + lane]);    // self loop
    int e0 = d_rowptr[gw], e1 = d_rowptr[gw + 1];
    int e = e0;
    for (; e + 4 <= e1; e += 4) {
        int s0 = d_col[e], s1 = d_col[e + 1], s2 = d_col[e + 2], s3 = d_col[e + 3];
        uint2 v0 = __ldg(&g2[(size_t)s0 * 32 + lane]);
        uint2 v1 = __ldg(&g2[(size_t)s1 * 32 + lane]);
        uint2 v2 = __ldg(&g2[(size_t)s2 * 32 + lane]);
        uint2 v3 = __ldg(&g2[(size_t)s3 * 32 + lane]);
        float4 f0 = h4_to_f4(v0), f1 = h4_to_f4(v1), f2 = h4_to_f4(v2), f3 = h4_to_f4(v3);
        s.x += (f0.x + f1.x) + (f2.x + f3.x);
        s.y += (f0.y + f1.y) + (f2.y + f3.y);
        s.z += (f0.z + f1.z) + (f2.z + f3.z);
        s.w += (f0.w + f1.w) + (f2.w + f3.w);
    }
    for (; e < e1; e++) {
        float4 f = h4_to_f4(__ldg(&g2[(size_t)d_col[e] * 32 + lane]));
        s.x += f.x; s.y += f.y; s.z += f.z; s.w += f.w;
    }
    float dj = d_dinv[gw];
    float4 bb = ((const float4*)b1)[lane];
    float4 o;
    o.x = fmaxf(fmaf(s.x, dj, bb.x), 0.f) * dj;
    o.y = fmaxf(fmaf(s.y, dj, bb.y), 0.f) * dj;
    o.z = fmaxf(fmaf(s.z, dj, bb.z), 0.f) * dj;
    o.w = fmaxf(fmaf(s.w, dj, bb.w), 0.f) * dj;
    ((uint2*)d_g2h)[(size_t)gw * 32 + lane] = f4_to_h4(o);
}

// ---------------- layer-2 aggregate: warp per node, atomic into pool ----------------
__global__ __launch_bounds__(256) void k_agg2(const int* __restrict__ batch) {
    int gw   = (blockIdx.x * blockDim.x + threadIdx.x) >> 5;
    int lane = threadIdx.x & 31;
    if (gw >= N_NODES) return;
    const uint2* g2 = (const uint2*)d_g2h;
    float4 s = h4_to_f4(g2[(size_t)gw * 32 + lane]);    // self loop
    int e0 = d_rowptr[gw], e1 = d_rowptr[gw + 1];
    int e = e0;
    for (; e + 4 <= e1; e += 4) {
        int s0 = d_col[e], s1 = d_col[e + 1], s2 = d_col[e + 2], s3 = d_col[e + 3];
        uint2 v0 = __ldg(&g2[(size_t)s0 * 32 + lane]);
        uint2 v1 = __ldg(&g2[(size_t)s1 * 32 + lane]);
        uint2 v2 = __ldg(&g2[(size_t)s2 * 32 + lane]);
        uint2 v3 = __ldg(&g2[(size_t)s3 * 32 + lane]);
        float4 f0 = h4_to_f4(v0), f1 = h4_to_f4(v1), f2 = h4_to_f4(v2), f3 = h4_to_f4(v3);
        s.x += (f0.x + f1.x) + (f2.x + f3.x);
        s.y += (f0.y + f1.y) + (f2.y + f3.y);
        s.z += (f0.z + f1.z) + (f2.z + f3.z);
        s.w += (f0.w + f1.w) + (f2.w + f3.w);
    }
    for (; e < e1; e++) {
        float4 f = h4_to_f4(__ldg(&g2[(size_t)d_col[e] * 32 + lane]));
        s.x += f.x; s.y += f.y; s.z += f.z; s.w += f.w;
    }
    float dj = d_dinv[gw];
    int bg = min(max(batch[gw], 0), N_GRAPHS - 1);
    float* p = &d_pool[bg * HID_C + lane * 4];
    atomicAdd(p + 0, s.x * dj);
    atomicAdd(p + 1, s.y * dj);
    atomicAdd(p + 2, s.z * dj);
    atomicAdd(p + 3, s.w * dj);
}

// ---------------- final: out = (pool/cnt) @ W2 + b2 ----------------
__global__ void k_final(const float* __restrict__ W2, const float* __restrict__ b2,
                        float* __restrict__ out) {
    __shared__ float ps[HID_C];
    int g = blockIdx.x;
    int t = threadIdx.x; // 128 threads
    int cnt = d_start[g + 1] - d_start[g];
    float inv = 1.0f / (float)max(cnt, 1);
    ps[t] = d_pool[g * HID_C + t];
    __syncthreads();
    if (t < OUT_C) {
        float sum = 0.f;
        #pragma unroll
        for (int k = 0; k < HID_C; k++)
            sum = fmaf(ps[k], W2[k * OUT_C + t], sum);
        out[g * OUT_C + t] = sum * inv + (cnt > 0 ? b2[t] : 0.f);
    }
}

// ---------------- launch ----------------
extern "C" void kernel_launch(void* const* d_in, const int* in_sizes, int n_in,
                              void* d_out, int out_size) {
    const float *x = nullptr, *W1 = nullptr, *b1 = nullptr, *W2 = nullptr, *b2 = nullptr;
    const int *edge = nullptr, *batch = nullptr;
    for (int i = 0; i < n_in; i++) {
        switch (in_sizes[i]) {
            case N_NODES * IN_C:  x     = (const float*)d_in[i]; break;
            case IN_C * HID_C:    W1    = (const float*)d_in[i]; break;
            case HID_C:           b1    = (const float*)d_in[i]; break;
            case HID_C * OUT_C:   W2    = (const float*)d_in[i]; break;
            case OUT_C:           b2    = (const float*)d_in[i]; break;
            case 2 * N_EDGES:     edge  = (const int*)d_in[i];   break;
            case N_NODES:         batch = (const int*)d_in[i];   break;
            default: break;
        }
    }

    cudaFuncSetAttribute(k_gemm1, cudaFuncAttributeMaxDynamicSharedMemorySize,
                         GEMM_SMEM_BYTES);

    k_init<<<(N_NODES + 255) / 256, 256>>>();
    k_hist<<<(N_EDGES + 255) / 256, 256>>>(edge);
    k_scanA<<<NBLK, 256>>>();
    k_scanB<<<1, 256>>>();
    k_scanC<<<NBLK, 256>>>();
    k_scatter<<<(N_EDGES + 255) / 256, 256>>>(edge);
    k_bound<<<(N_NODES + 255) / 256, 256>>>(batch);
    k_gemm1<<<(N_NODES + 127) / 128, 256, GEMM_SMEM_BYTES>>>(x, W1);
    k_agg1<<<(N_NODES + 7) / 8, 256>>>(b1);
    k_agg2<<<(N_NODES + 7) / 8, 256>>>(batch);
    k_final<<<N_GRAPHS, 128>>>(W2, b2, (float*)d_out);
}

// round 4
// speedup vs baseline: 1.3714x; 1.1896x over previous
#include <cuda_runtime.h>
#include <cuda_fp16.h>
#include <mma.h>
#include <math.h>

using namespace nvcuda;

#define N_NODES  50000
#define N_EDGES  600000
#define N_GRAPHS 64
#define IN_C  128
#define HID_C 128
#define OUT_C 64
#define NBLK  196            // ceil(50000/256)

// ---------------- scratch (device globals; no allocation allowed) ----------------
__device__ int    d_cnt[N_NODES];
__device__ int    d_rowptr[N_NODES + 1];
__device__ int    d_cursor[N_NODES];
__device__ int    d_part[NBLK];
__device__ int    d_col[N_EDGES];
__device__ float  d_dinv[N_NODES];
__device__ __half d_gh [N_NODES * HID_C];   // dinv * (x @ W1), fp16
__device__ __half d_g2h[N_NODES * HID_C];   // dinv * relu(...), fp16
__device__ float  d_pool[N_GRAPHS * HID_C];
__device__ int    d_start[N_GRAPHS + 1];

// ---------------- helpers ----------------
__device__ __forceinline__ float4 h4_to_f4(uint2 u) {
    __half2 a = *(__half2*)&u.x, b = *(__half2*)&u.y;
    float2 fa = __half22float2(a), fb = __half22float2(b);
    return make_float4(fa.x, fa.y, fb.x, fb.y);
}
__device__ __forceinline__ uint2 f4_to_h4(float4 v) {
    __half2 a = __floats2half2_rn(v.x, v.y), b = __floats2half2_rn(v.z, v.w);
    uint2 u; u.x = *(unsigned*)&a; u.y = *(unsigned*)&b; return u;
}

// ---------------- init ----------------
__global__ void k_init() {
    int i = blockIdx.x * blockDim.x + threadIdx.x;
    if (i < N_NODES) d_cnt[i] = 0;
    if (i < N_GRAPHS * HID_C) d_pool[i] = 0.0f;
}

// ---------------- histogram over dst ----------------
__global__ void k_hist(const int* __restrict__ edge) {
    int e = blockIdx.x * blockDim.x + threadIdx.x;
    if (e >= N_EDGES) return;
    unsigned dst = (unsigned)edge[N_EDGES + e];
    if (dst < N_NODES) atomicAdd(&d_cnt[dst], 1);
}

// ---------------- scan A: per-block excl scan + block totals ----------------
__global__ __launch_bounds__(256) void k_scanA() {
    __shared__ int wsum[8];
    int tid = threadIdx.x, lane = tid & 31, wid = tid >> 5;
    int i = blockIdx.x * 256 + tid;
    int v = (i < N_NODES) ? d_cnt[i] : 0;
    int x = v;
    #pragma unroll
    for (int d = 1; d < 32; d <<= 1) {
        int t = __shfl_up_sync(0xffffffffu, x, d);
        if (lane >= d) x += t;
    }
    if (lane == 31) wsum[wid] = x;
    __syncthreads();
    if (wid == 0 && lane < 8) {
        int y = wsum[lane];
        #pragma unroll
        for (int d = 1; d < 8; d <<= 1) {
            int t = __shfl_up_sync(0x000000ffu, y, d);
            if (lane >= d) y += t;
        }
        wsum[lane] = y;
    }
    __syncthreads();
    int excl = (x - v) + (wid > 0 ? wsum[wid - 1] : 0);
    if (i < N_NODES) d_cursor[i] = excl;
    if (tid == 0) d_part[blockIdx.x] = wsum[7];
}

// ---------------- scan B: scan 196 block totals ----------------
__global__ __launch_bounds__(256) void k_scanB() {
    __shared__ int s[256];
    int t = threadIdx.x;
    int v = (t < NBLK) ? d_part[t] : 0;
    s[t] = v; __syncthreads();
    for (int off = 1; off < 256; off <<= 1) {
        int u = (t >= off) ? s[t - off] : 0;
        __syncthreads();
        s[t] += u;
        __syncthreads();
    }
    if (t < NBLK) d_part[t] = s[t] - v;
    if (t == 255) d_rowptr[N_NODES] = s[255];
}

// ---------------- scan C: fixup + dinv + graph boundaries ----------------
__global__ __launch_bounds__(256) void k_scanC(const int* __restrict__ batch) {
    int i = blockIdx.x * 256 + threadIdx.x;
    if (i >= N_NODES) return;
    int v = d_cursor[i] + d_part[blockIdx.x];
    d_rowptr[i] = v;
    d_cursor[i] = v;
    d_dinv[i] = rsqrtf((float)(d_cnt[i] + 1));
    int b  = min(max(batch[i], 0), N_GRAPHS - 1);
    int bp = (i == 0) ? -1 : min(max(batch[i - 1], 0), N_GRAPHS - 1);
    for (int gg = bp + 1; gg <= b; gg++) d_start[gg] = i;
    if (i == N_NODES - 1)
        for (int gg = b + 1; gg <= N_GRAPHS; gg++) d_start[gg] = N_NODES;
}

// ---------------- CSR scatter ----------------
__global__ void k_scatter(const int* __restrict__ edge) {
    int e = blockIdx.x * blockDim.x + threadIdx.x;
    if (e >= N_EDGES) return;
    unsigned src = (unsigned)edge[e];
    unsigned dst = (unsigned)edge[N_EDGES + e];
    if (src >= N_NODES || dst >= N_NODES) return;
    int p = atomicAdd(&d_cursor[dst], 1);
    d_col[p] = (int)src;
}

// ---------------- GEMM1 (tensor cores): d_gh = fp16( dinv * (x @ W1) ) ----------------
// 128x128 tile/block, 8 warps, wmma 16x16x16 fp16 -> fp32.
#define ASTR 136   // half stride, 272B rows (16B-multiple), breaks ldmatrix conflicts
#define GEMM_SMEM_BYTES (2 * 128 * ASTR * 2)   // A + B fp16 = 69632; C f32 (65536) aliases
__global__ __launch_bounds__(256) void k_gemm1(const float* __restrict__ x,
                                               const float* __restrict__ W1) {
    extern __shared__ char smraw[];
    __half* As = (__half*)smraw;               // [128][ASTR]
    __half* Bs = As + 128 * ASTR;              // [128][ASTR] (W1 row-major: k-major)
    float*  Cs = (float*)smraw;                // [128][128], reused after mma
    int row0 = blockIdx.x * 128;
    int tid = threadIdx.x, wid = tid >> 5;

    // stage x tile (fp32 -> fp16)
    for (int i = tid; i < 4096; i += 256) {
        int r = i >> 5, c4 = i & 31;
        int gr = row0 + r;
        float4 v = make_float4(0.f, 0.f, 0.f, 0.f);
        if (gr < N_NODES) v = ((const float4*)(x + (size_t)gr * IN_C))[c4];
        *(uint2*)&As[r * ASTR + c4 * 4] = f4_to_h4(v);
    }
    // stage W1 (fp32 -> fp16)
    for (int i = tid; i < 4096; i += 256) {
        int r = i >> 5, c4 = i & 31;
        float4 v = ((const float4*)W1)[i];
        *(uint2*)&Bs[r * ASTR + c4 * 4] = f4_to_h4(v);
    }
    __syncthreads();

    wmma::fragment<wmma::accumulator, 16, 16, 16, float> acc[8];
    #pragma unroll
    for (int n = 0; n < 8; n++) wmma::fill_fragment(acc[n], 0.0f);

    #pragma unroll
    for (int kk = 0; kk < 8; kk++) {
        wmma::fragment<wmma::matrix_a, 16, 16, 16, __half, wmma::row_major> af;
        wmma::load_matrix_sync(af, &As[(wid * 16) * ASTR + kk * 16], ASTR);
        #pragma unroll
        for (int n = 0; n < 8; n++) {
            wmma::fragment<wmma::matrix_b, 16, 16, 16, __half, wmma::row_major> bf;
            wmma::load_matrix_sync(bf, &Bs[(kk * 16) * ASTR + n * 16], ASTR);
            wmma::mma_sync(acc[n], af, bf, acc[n]);
        }
    }
    __syncthreads();   // done reading As/Bs; Cs aliases them

    #pragma unroll
    for (int n = 0; n < 8; n++)
        wmma::store_matrix_sync(&Cs[(wid * 16) * 128 + n * 16], acc[n], 128,
                                wmma::mem_row_major);
    __syncthreads();

    // epilogue: scale by dinv, pack fp16, write out
    for (int i = tid; i < 4096; i += 256) {
        int r = i >> 5, c4 = i & 31;
        int gr = row0 + r;
        if (gr < N_NODES) {
            float dv = d_dinv[gr];
            float4 v = *(float4*)&Cs[r * 128 + c4 * 4];
            v.x *= dv; v.y *= dv; v.z *= dv; v.w *= dv;
            *(uint2*)&d_gh[(size_t)gr * HID_C + c4 * 4] = f4_to_h4(v);
        }
    }
}

// ---------------- layer-1 aggregate: warp per node ----------------
__global__ __launch_bounds__(256) void k_agg1(const float* __restrict__ b1) {
    int gw   = (blockIdx.x * blockDim.x + threadIdx.x) >> 5;
    int lane = threadIdx.x & 31;
    if (gw >= N_NODES) return;
    const uint2* g2 = (const uint2*)d_gh;
    float4 s = h4_to_f4(g2[(size_t)gw * 32 + lane]);
    int e0 = d_rowptr[gw], e1 = d_rowptr[gw + 1];
    int e = e0;
    for (; e + 4 <= e1; e += 4) {
        int s0 = __ldg(&d_col[e]),     s1 = __ldg(&d_col[e + 1]);
        int s2 = __ldg(&d_col[e + 2]), s3 = __ldg(&d_col[e + 3]);
        uint2 v0 = __ldg(&g2[(size_t)s0 * 32 + lane]);
        uint2 v1 = __ldg(&g2[(size_t)s1 * 32 + lane]);
        uint2 v2 = __ldg(&g2[(size_t)s2 * 32 + lane]);
        uint2 v3 = __ldg(&g2[(size_t)s3 * 32 + lane]);
        float4 f0 = h4_to_f4(v0), f1 = h4_to_f4(v1), f2 = h4_to_f4(v2), f3 = h4_to_f4(v3);
        s.x += (f0.x + f1.x) + (f2.x + f3.x);
        s.y += (f0.y + f1.y) + (f2.y + f3.y);
        s.z += (f0.z + f1.z) + (f2.z + f3.z);
        s.w += (f0.w + f1.w) + (f2.w + f3.w);
    }
    for (; e < e1; e++) {
        float4 f = h4_to_f4(__ldg(&g2[(size_t)__ldg(&d_col[e]) * 32 + lane]));
        s.x += f.x; s.y += f.y; s.z += f.z; s.w += f.w;
    }
    float dj = d_dinv[gw];
    float4 bb = ((const float4*)b1)[lane];
    float4 o;
    o.x = fmaxf(fmaf(s.x, dj, bb.x), 0.f) * dj;
    o.y = fmaxf(fmaf(s.y, dj, bb.y), 0.f) * dj;
    o.z = fmaxf(fmaf(s.z, dj, bb.z), 0.f) * dj;
    o.w = fmaxf(fmaf(s.w, dj, bb.w), 0.f) * dj;
    ((uint2*)d_g2h)[(size_t)gw * 32 + lane] = f4_to_h4(o);
}

// ---------------- layer-2 aggregate + pool atomics ----------------
__global__ __launch_bounds__(256) void k_agg2(const int* __restrict__ batch) {
    int gw   = (blockIdx.x * blockDim.x + threadIdx.x) >> 5;
    int lane = threadIdx.x & 31;
    if (gw >= N_NODES) return;
    const uint2* g2 = (const uint2*)d_g2h;
    float4 s = h4_to_f4(g2[(size_t)gw * 32 + lane]);
    int e0 = d_rowptr[gw], e1 = d_rowptr[gw + 1];
    int e = e0;
    for (; e + 4 <= e1; e += 4) {
        int s0 = __ldg(&d_col[e]),     s1 = __ldg(&d_col[e + 1]);
        int s2 = __ldg(&d_col[e + 2]), s3 = __ldg(&d_col[e + 3]);
        uint2 v0 = __ldg(&g2[(size_t)s0 * 32 + lane]);
        uint2 v1 = __ldg(&g2[(size_t)s1 * 32 + lane]);
        uint2 v2 = __ldg(&g2[(size_t)s2 * 32 + lane]);
        uint2 v3 = __ldg(&g2[(size_t)s3 * 32 + lane]);
        float4 f0 = h4_to_f4(v0), f1 = h4_to_f4(v1), f2 = h4_to_f4(v2), f3 = h4_to_f4(v3);
        s.x += (f0.x + f1.x) + (f2.x + f3.x);
        s.y += (f0.y + f1.y) + (f2.y + f3.y);
        s.z += (f0.z + f1.z) + (f2.z + f3.z);
        s.w += (f0.w + f1.w) + (f2.w + f3.w);
    }
    for (; e < e1; e++) {
        float4 f = h4_to_f4(__ldg(&g2[(size_t)__ldg(&d_col[e]) * 32 + lane]));
        s.x += f.x; s.y += f.y; s.z += f.z; s.w += f.w;
    }
    float dj = d_dinv[gw];
    int bg = min(max(batch[gw], 0), N_GRAPHS - 1);
    float* p = &d_pool[bg * HID_C + lane * 4];
    atomicAdd(p + 0, s.x * dj);
    atomicAdd(p + 1, s.y * dj);
    atomicAdd(p + 2, s.z * dj);
    atomicAdd(p + 3, s.w * dj);
}

// ---------------- final: out = (pool/cnt) @ W2 + b2 ----------------
__global__ void k_final(const float* __restrict__ W2, const float* __restrict__ b2,
                        float* __restrict__ out) {
    __shared__ float ps[HID_C];
    int g = blockIdx.x;
    int t = threadIdx.x; // 128 threads
    int cnt = d_start[g + 1] - d_start[g];
    float inv = 1.0f / (float)max(cnt, 1);
    ps[t] = d_pool[g * HID_C + t];
    __syncthreads();
    if (t < OUT_C) {
        float sum = 0.f;
        #pragma unroll
        for (int k = 0; k < HID_C; k++)
            sum = fmaf(ps[k], W2[k * OUT_C + t], sum);
        out[g * OUT_C + t] = sum * inv + (cnt > 0 ? b2[t] : 0.f);
    }
}

// ---------------- launch ----------------
extern "C" void kernel_launch(void* const* d_in, const int* in_sizes, int n_in,
                              void* d_out, int out_size) {
    const float *x = nullptr, *W1 = nullptr, *b1 = nullptr, *W2 = nullptr, *b2 = nullptr;
    const int *edge = nullptr, *batch = nullptr;
    for (int i = 0; i < n_in; i++) {
        switch (in_sizes[i]) {
            case N_NODES * IN_C:  x     = (const float*)d_in[i]; break;
            case IN_C * HID_C:    W1    = (const float*)d_in[i]; break;
            case HID_C:           b1    = (const float*)d_in[i]; break;
            case HID_C * OUT_C:   W2    = (const float*)d_in[i]; break;
            case OUT_C:           b2    = (const float*)d_in[i]; break;
            case 2 * N_EDGES:     edge  = (const int*)d_in[i];   break;
            case N_NODES:         batch = (const int*)d_in[i];   break;
            default: break;
        }
    }

    cudaFuncSetAttribute(k_gemm1, cudaFuncAttributeMaxDynamicSharedMemorySize,
                         GEMM_SMEM_BYTES);

    k_init<<<(N_NODES + 255) / 256, 256>>>();
    k_hist<<<(N_EDGES + 255) / 256, 256>>>(edge);
    k_scanA<<<NBLK, 256>>>();
    k_scanB<<<1, 256>>>();
    k_scanC<<<NBLK, 256>>>(batch);
    k_scatter<<<(N_EDGES + 255) / 256, 256>>>(edge);
    k_gemm1<<<(N_NODES + 127) / 128, 256, GEMM_SMEM_BYTES>>>(x, W1);
    k_agg1<<<(N_NODES + 7) / 8, 256>>>(b1);
    k_agg2<<<(N_NODES + 7) / 8, 256>>>(batch);
    k_final<<<N_GRAPHS, 128>>>(W2, b2, (float*)d_out);
}